// round 15
// baseline (speedup 1.0000x reference)
#include <cuda_runtime.h>
#include <cuda_bf16.h>

#define HH 56
#define WW 56
#define PP 3136   // HH*WW
#define BB 8
#define CC 64
#define KK 9      // 3x3

// Scratch (device globals)
__device__ float g_xT[BB * PP * CC];            // x transposed: [b][p][c]
__device__ float g_invn[BB * PP];               // 1/||x[b,:,p]||
__device__ int   g_sel[BB * PP * KK];           // sorted GLOBAL gather indices
__device__ unsigned short g_wBh[KK * 4096];     // W bf16 hi:  [k][o*64+c]
__device__ unsigned short g_wBl[KK * 4096];     // W bf16 lo residual
__device__ unsigned short g_xh[BB * PP * CC];   // x bf16 hi:  [gp][c] (128B rows)
__device__ unsigned short g_xl[BB * PP * CC];   // x bf16 lo residual

// ---------------------------------------------------------------------------
// helpers
// ---------------------------------------------------------------------------
__device__ __forceinline__ float2 ffma2(float2 a, float2 b, float2 c) {
    unsigned long long A, Bv, Cv;
    A  = *reinterpret_cast<unsigned long long*>(&a);
    Bv = *reinterpret_cast<unsigned long long*>(&b);
    Cv = *reinterpret_cast<unsigned long long*>(&c);
    unsigned long long R;
    asm("fma.rn.f32x2 %0, %1, %2, %3;" : "=l"(R) : "l"(A), "l"(Bv), "l"(Cv));
    return *reinterpret_cast<float2*>(&R);
}

__device__ __forceinline__ void cp16(void* sdst, const void* gsrc) {
    unsigned sa = (unsigned)__cvta_generic_to_shared(sdst);
    asm volatile("cp.async.cg.shared.global [%0], [%1], 16;\n" :: "r"(sa), "l"(gsrc));
}

// pack {lo, hi} floats -> bf16x2 (lo in low 16 bits)
__device__ __forceinline__ unsigned bfpack(float lo, float hi) {
    unsigned r;
    asm("cvt.rn.bf16x2.f32 %0, %1, %2;" : "=r"(r) : "f"(hi), "f"(lo));
    return r;
}

__device__ __forceinline__ void ldsm4(unsigned* r, unsigned a) {
    asm volatile("ldmatrix.sync.aligned.m8n8.x4.shared.b16 {%0,%1,%2,%3}, [%4];\n"
        : "=r"(r[0]), "=r"(r[1]), "=r"(r[2]), "=r"(r[3]) : "r"(a));
}

__device__ __forceinline__ void mma_bf16(float* d, const unsigned* a, const unsigned* b) {
    asm volatile(
        "mma.sync.aligned.m16n8k16.row.col.f32.bf16.bf16.f32 "
        "{%0,%1,%2,%3}, {%4,%5,%6,%7}, {%8,%9}, {%0,%1,%2,%3};\n"
        : "+f"(d[0]), "+f"(d[1]), "+f"(d[2]), "+f"(d[3])
        : "r"(a[0]), "r"(a[1]), "r"(a[2]), "r"(a[3]), "r"(b[0]), "r"(b[1]));
}

// ---------------------------------------------------------------------------
// 1) prep: blocks [0,392) transpose 64px x 64ch + invnorm + bf16 hi/lo split;
//    blocks [392,401) weight split
// ---------------------------------------------------------------------------
__global__ void __launch_bounds__(256)
prep2_kernel(const float* __restrict__ x, const float* __restrict__ wgt) {
    const int id = blockIdx.x;
    const int t = threadIdx.x;

    if (id >= 392) {            // --- weight bf16 hi/lo split, [k][o*64+c] ---
        int k = id - 392;
#pragma unroll
        for (int s = 0; s < 16; s++) {
            int r = t * 16 + s;            // 0..4095
            int o = r >> 6, c = r & 63;
            float w = wgt[o * 576 + c * 9 + k];
            unsigned hp = bfpack(w, 0.0f);
            float res = w - __uint_as_float(hp << 16);
            unsigned lp = bfpack(res, 0.0f);
            g_wBh[k * 4096 + r] = (unsigned short)(hp & 0xFFFFu);
            g_wBl[k * 4096 + r] = (unsigned short)(lp & 0xFFFFu);
        }
        return;
    }

    __shared__ float s[64][67];
    int b = id / 49, pt = id - b * 49;
    int p0 = pt * 64;
    const float* xb = x + (size_t)b * CC * PP;
    float* xTb = g_xT + (size_t)b * PP * CC;

    const int v = t & 15, c0 = t >> 4;
    float4 ld[4];
#pragma unroll
    for (int i = 0; i < 4; i++)
        ld[i] = *(const float4*)(xb + (size_t)(c0 + 16 * i) * PP + p0 + 4 * v);
#pragma unroll
    for (int i = 0; i < 4; i++) {
        int c = c0 + 16 * i;
        s[c][4 * v + 0] = ld[i].x; s[c][4 * v + 1] = ld[i].y;
        s[c][4 * v + 2] = ld[i].z; s[c][4 * v + 3] = ld[i].w;
    }
    __syncthreads();

    const int p_l = t >> 4, v2 = t & 15;
#pragma unroll
    for (int i = 0; i < 4; i++) {
        int p = p_l + 16 * i;
        float4 o;
        o.x = s[4 * v2 + 0][p]; o.y = s[4 * v2 + 1][p];
        o.z = s[4 * v2 + 2][p]; o.w = s[4 * v2 + 3][p];
        size_t gp = (size_t)(b * PP + p0 + p);
        *(float4*)(xTb + (size_t)(p0 + p) * CC + 4 * v2) = o;

        // bf16 hi/lo split (identical math to old conv staging)
        unsigned h01 = bfpack(o.x, o.y);
        unsigned h23 = bfpack(o.z, o.w);
        float r0 = o.x - __uint_as_float(h01 << 16);
        float r1 = o.y - __uint_as_float(h01 & 0xFFFF0000u);
        float r2 = o.z - __uint_as_float(h23 << 16);
        float r3 = o.w - __uint_as_float(h23 & 0xFFFF0000u);
        unsigned l01 = bfpack(r0, r1);
        unsigned l23 = bfpack(r2, r3);
        *(uint2*)(g_xh + gp * CC + 4 * v2) = make_uint2(h01, h23);
        *(uint2*)(g_xl + gp * CC + 4 * v2) = make_uint2(l01, l23);

        float sum = o.x * o.x + o.y * o.y + o.z * o.z + o.w * o.w;
        sum += __shfl_xor_sync(0xffffffffu, sum, 1);
        sum += __shfl_xor_sync(0xffffffffu, sum, 2);
        sum += __shfl_xor_sync(0xffffffffu, sum, 4);
        sum += __shfl_xor_sync(0xffffffffu, sum, 8);
        if (v2 == 0) g_invn[b * PP + p0 + p] = 1.0f / sqrtf(sum);
    }
}

// ---------------------------------------------------------------------------
// 3) simsel (unchanged; stores GLOBAL pixel indices b*PP + pick)
// ---------------------------------------------------------------------------
#define SROW 68

__global__ void __launch_bounds__(256)
simsel2_kernel() {
    __shared__ __align__(16) float sn[60 * SROW];

    const int t = threadIdx.x;
    const int j0 = blockIdx.x * 8;
    const int i  = blockIdx.y;
    const int b  = blockIdx.z;
    const float* xb   = g_xT + (size_t)b * PP * CC;
    const float* invb = g_invn + b * PP;

    {
        int slot = t >> 2, q = t & 3;
        if (slot < 60) {
            int ri = slot / 12, rj = slot - ri * 12;
            int gi = i - 2 + ri, gj = j0 - 2 + rj;
            if (gi >= 0 && gi < HH && gj >= 0 && gj < WW) {
                int gp = gi * WW + gj;
                const float* src = xb + (size_t)gp * CC;
                float iv = invb[gp];
                float* dst = sn + slot * SROW;
#pragma unroll
                for (int s = 0; s < 4; s++) {
                    int chunk = q + 4 * s;
                    float4 v = *(const float4*)(src + chunk * 4);
                    v.x *= iv; v.y *= iv; v.z *= iv; v.w *= iv;
                    *(float4*)(dst + 4 * ((chunk + ri) & 15)) = v;
                }
            }
        }
    }
    __syncthreads();

    const int lane = t & 31, w = t >> 5;
    const int j = j0 + w;

    int lo_i = (i - 2 < 0) ? 0 : i - 2;
    int hi_i = (i + 2 > HH - 1) ? HH - 1 : i + 2;
    int lo_j = (j - 2 < 0) ? 0 : j - 2;
    int hi_j = (j + 2 > WW - 1) ? WW - 1 : j + 2;
    int nrow = hi_i - lo_i + 1, ncol = hi_j - lo_j + 1;
    int ncand = nrow * ncol;

    unsigned mult = (65536u + (unsigned)ncol - 1) / (unsigned)ncol;
    int cr = (int)(((unsigned)lane * mult) >> 16);
    int cc = lane - cr * ncol;
    int ri = (lo_i - (i - 2)) + cr;
    int rj = (lo_j - (j0 - 2)) + cc;
    int slot = ri * 12 + rj;
    int rot_c = ri;
    if (lane >= ncand) { slot = 0; rot_c = 0; }
    int cpix = b * PP + (lo_i + cr) * WW + (lo_j + cc);   // GLOBAL index

    const float* crow = sn + slot * SROW;
    const float* prow = sn + (2 * 12 + (w + 2)) * SROW;

    int idx_c = rot_c & 15;
    int idx_p = 2;

    float2 aA = make_float2(0.f, 0.f), aB = make_float2(0.f, 0.f);
#pragma unroll
    for (int s = 0; s < 16; s++) {
        float4 cv = *(const float4*)(crow + 4 * idx_c);
        float4 pv = *(const float4*)(prow + 4 * idx_p);
        aA = ffma2(make_float2(cv.x, cv.y), make_float2(pv.x, pv.y), aA);
        aB = ffma2(make_float2(cv.z, cv.w), make_float2(pv.z, pv.w), aB);
        idx_c = (idx_c + 1) & 15;
        idx_p = (idx_p + 1) & 15;
    }
    float sim = (aA.x + aB.x) + (aA.y + aB.y);

    unsigned ub = __float_as_uint(sim);
    unsigned key = (ub & 0x80000000u) ? ~ub : (ub | 0x80000000u);
    if (lane >= ncand) key = 0xFFFFFFFFu;

    int mypick = 0;
#pragma unroll
    for (int r = 0; r < KK; r++) {
        unsigned m = __reduce_min_sync(0xffffffffu, key);
        unsigned ball = __ballot_sync(0xffffffffu, key == m);
        int bl = __ffs(ball) - 1;
        int wc = __shfl_sync(0xffffffffu, cpix, bl);
        if (lane == bl) key = 0xFFFFFFFFu;
        if (lane == r) mypick = wc;
    }

    int rank = 0;
#pragma unroll
    for (int r = 0; r < KK; r++) {
        int other = __shfl_sync(0xffffffffu, mypick, r);
        if (lane < KK && r != lane && other < mypick) rank++;
    }
    if (lane < KK)
        g_sel[((size_t)(b * PP + i * WW + j)) * KK + rank] = mypick;
}

// ---------------------------------------------------------------------------
// 4) conv_mma: HMMA split-product GEMM; A staged via pure cp.async from the
//    PRE-SPLIT bf16 images (no fp32 loads, no cvt in the hot loop).
// ---------------------------------------------------------------------------
#define CM_SEL  0
#define CM_GH   4608                  // 128 rows * 144B
#define CM_GL   (CM_GH + 18432)
#define CM_WH   (CM_GL + 18432)       // 64 rows * 144B
#define CM_WL   (CM_WH + 9216)
#define CM_SMEM (CM_WL + 9216)        // 59904 B

__global__ void __launch_bounds__(256)
conv_mma_kernel(float* __restrict__ out) {
    extern __shared__ __align__(128) char sm[];
    unsigned sbase = (unsigned)__cvta_generic_to_shared(sm);
    int* selS = (int*)(sm + CM_SEL);

    const int tid = threadIdx.x;
    const int wid = tid >> 5, lane = tid & 31;
    const int tile = blockIdx.x;           // 196 tiles of 128 pixels

    for (int t2 = tid; t2 < 128 * KK; t2 += 256)
        selS[t2] = g_sel[(size_t)tile * 128 * KK + t2];

    const int qrow = tid >> 1;             // 0..127 pixel row (staging)
    const int half = tid & 1;              // 64B half of the 128B bf16 row

    const int m0 = (wid & 3) * 32;         // warp pixel offset
    const int n0 = (wid >> 2) * 32;        // warp o offset

    // ldmatrix per-lane addresses
    const int arow = (lane & 7) + 8 * ((lane >> 3) & 1);
    const unsigned acol = (unsigned)(lane >> 4) * 16;
    const int brow = (lane & 7) + 8 * (lane >> 4);
    const unsigned bcol = (unsigned)((lane >> 3) & 1) * 16;

    const unsigned aAH0 = sbase + CM_GH + (unsigned)(m0 + arow) * 144 + acol;
    const unsigned aAH1 = aAH0 + 16 * 144;
    const unsigned aAL0 = aAH0 + (CM_GL - CM_GH);
    const unsigned aAL1 = aAH1 + (CM_GL - CM_GH);
    const unsigned aBH0 = sbase + CM_WH + (unsigned)(n0 + brow) * 144 + bcol;
    const unsigned aBH1 = aBH0 + 16 * 144;
    const unsigned aBL0 = aBH0 + (CM_WL - CM_WH);
    const unsigned aBL1 = aBH1 + (CM_WL - CM_WH);

    float acc[2][4][4];
#pragma unroll
    for (int mf = 0; mf < 2; mf++)
#pragma unroll
        for (int nf = 0; nf < 4; nf++)
#pragma unroll
            for (int r = 0; r < 4; r++) acc[mf][nf][r] = 0.0f;

    __syncthreads();   // selS visible

    for (int kc = 0; kc < KK; kc++) {
        // --- stage W hi/lo via cp.async ---
#pragma unroll
        for (int i = 0; i < 2; i++) {
            int e = tid + i * 256;             // 0..511
            int row = e >> 3, c16 = e & 7;
            unsigned doff = (unsigned)row * 144 + (unsigned)c16 * 16;
            cp16(sm + CM_WH + doff, (const char*)g_wBh + (size_t)kc * 8192 + (size_t)e * 16);
            cp16(sm + CM_WL + doff, (const char*)g_wBl + (size_t)kc * 8192 + (size_t)e * 16);
        }
        // --- stage A hi/lo via cp.async from pre-split bf16 rows ---
        {
            int rowg = selS[qrow * KK + kc];
            const char* srch = (const char*)g_xh + (size_t)rowg * 128 + half * 64;
            const char* srcl = (const char*)g_xl + (size_t)rowg * 128 + half * 64;
            unsigned doff = (unsigned)qrow * 144 + (unsigned)half * 64;
#pragma unroll
            for (int i = 0; i < 4; i++) {
                cp16(sm + CM_GH + doff + i * 16, srch + i * 16);
                cp16(sm + CM_GL + doff + i * 16, srcl + i * 16);
            }
        }
        asm volatile("cp.async.commit_group;\n");
        asm volatile("cp.async.wait_group 0;\n");
        __syncthreads();

        // --- compute: 4 k-steps of 16 ---
#pragma unroll
        for (int s = 0; s < 4; s++) {
            unsigned ks = (unsigned)s * 32;
            unsigned ah0[4], ah1[4], b0[4], b1[4], t0[4], t1[4];
            ldsm4(ah0, aAH0 + ks);
            ldsm4(ah1, aAH1 + ks);
            ldsm4(b0, aBH0 + ks);          // {nf0.b0, nf0.b1, nf1.b0, nf1.b1}
            ldsm4(b1, aBH1 + ks);          // nf2, nf3
            // Ah * Bh
            mma_bf16(acc[0][0], ah0, b0);     mma_bf16(acc[0][1], ah0, b0 + 2);
            mma_bf16(acc[0][2], ah0, b1);     mma_bf16(acc[0][3], ah0, b1 + 2);
            mma_bf16(acc[1][0], ah1, b0);     mma_bf16(acc[1][1], ah1, b0 + 2);
            mma_bf16(acc[1][2], ah1, b1);     mma_bf16(acc[1][3], ah1, b1 + 2);
            // Al * Bh
            ldsm4(t0, aAL0 + ks);
            ldsm4(t1, aAL1 + ks);
            mma_bf16(acc[0][0], t0, b0);      mma_bf16(acc[0][1], t0, b0 + 2);
            mma_bf16(acc[0][2], t0, b1);      mma_bf16(acc[0][3], t0, b1 + 2);
            mma_bf16(acc[1][0], t1, b0);      mma_bf16(acc[1][1], t1, b0 + 2);
            mma_bf16(acc[1][2], t1, b1);      mma_bf16(acc[1][3], t1, b1 + 2);
            // Ah * Bl
            ldsm4(b0, aBL0 + ks);
            ldsm4(b1, aBL1 + ks);
            mma_bf16(acc[0][0], ah0, b0);     mma_bf16(acc[0][1], ah0, b0 + 2);
            mma_bf16(acc[0][2], ah0, b1);     mma_bf16(acc[0][3], ah0, b1 + 2);
            mma_bf16(acc[1][0], ah1, b0);     mma_bf16(acc[1][1], ah1, b0 + 2);
            mma_bf16(acc[1][2], ah1, b1);     mma_bf16(acc[1][3], ah1, b1 + 2);
        }
        __syncthreads();    // all reads done before next chunk overwrites
    }

    // --- epilogue: C[px][o] -> out[b][o][p] ---
#pragma unroll
    for (int mf = 0; mf < 2; mf++) {
        int q0p = tile * 128 + m0 + 16 * mf + (lane >> 2);
        int q1p = q0p + 8;
        int b0i = q0p / PP, b1i = q1p / PP;
        float* ptr0 = out + (size_t)b0i * CC * PP + (q0p - b0i * PP);
        float* ptr1 = out + (size_t)b1i * CC * PP + (q1p - b1i * PP);
#pragma unroll
        for (int nf = 0; nf < 4; nf++) {
            int o = n0 + 8 * nf + (lane & 3) * 2;
            ptr0[(size_t)o * PP]       = acc[mf][nf][0];
            ptr0[(size_t)(o + 1) * PP] = acc[mf][nf][1];
            ptr1[(size_t)o * PP]       = acc[mf][nf][2];
            ptr1[(size_t)(o + 1) * PP] = acc[mf][nf][3];
        }
    }
}

// ---------------------------------------------------------------------------
extern "C" void kernel_launch(void* const* d_in, const int* in_sizes, int n_in,
                              void* d_out, int out_size) {
    const float* x = (const float*)d_in[0];   // [8,64,56,56]
    const float* w = (const float*)d_in[1];   // [64,64,3,3]
    float* out = (float*)d_out;               // [8,64,56,56]

    cudaFuncSetAttribute(conv_mma_kernel,
                         cudaFuncAttributeMaxDynamicSharedMemorySize, CM_SMEM);

    prep2_kernel<<<401, 256>>>(x, w);
    simsel2_kernel<<<dim3(7, 56, 8), 256>>>();
    conv_mma_kernel<<<196, 256, CM_SMEM>>>(out);
}

// round 16
// speedup vs baseline: 1.5080x; 1.5080x over previous
#include <cuda_runtime.h>
#include <cuda_bf16.h>

#define HH 56
#define WW 56
#define PP 3136   // HH*WW
#define BB 8
#define CC 64
#define KK 9      // 3x3

// Scratch (device globals)
__device__ float g_xT[BB * PP * CC];            // x transposed: [b][p][c]
__device__ float g_invn[BB * PP];               // 1/||x[b,:,p]||
__device__ int   g_sel[BB * PP * KK];           // sorted GLOBAL gather indices
__device__ unsigned short g_wBh[KK * 4096];     // W bf16 hi:  [k][o*64+c]
__device__ unsigned short g_wBl[KK * 4096];     // W bf16 lo residual

// ---------------------------------------------------------------------------
// helpers
// ---------------------------------------------------------------------------
__device__ __forceinline__ float2 ffma2(float2 a, float2 b, float2 c) {
    unsigned long long A, Bv, Cv;
    A  = *reinterpret_cast<unsigned long long*>(&a);
    Bv = *reinterpret_cast<unsigned long long*>(&b);
    Cv = *reinterpret_cast<unsigned long long*>(&c);
    unsigned long long R;
    asm("fma.rn.f32x2 %0, %1, %2, %3;" : "=l"(R) : "l"(A), "l"(Bv), "l"(Cv));
    return *reinterpret_cast<float2*>(&R);
}

__device__ __forceinline__ void cp16(void* sdst, const void* gsrc) {
    unsigned sa = (unsigned)__cvta_generic_to_shared(sdst);
    asm volatile("cp.async.cg.shared.global [%0], [%1], 16;\n" :: "r"(sa), "l"(gsrc));
}

// pack {lo, hi} floats -> bf16x2 (lo in low 16 bits)
__device__ __forceinline__ unsigned bfpack(float lo, float hi) {
    unsigned r;
    asm("cvt.rn.bf16x2.f32 %0, %1, %2;" : "=r"(r) : "f"(hi), "f"(lo));
    return r;
}

__device__ __forceinline__ void ldsm4(unsigned* r, unsigned a) {
    asm volatile("ldmatrix.sync.aligned.m8n8.x4.shared.b16 {%0,%1,%2,%3}, [%4];\n"
        : "=r"(r[0]), "=r"(r[1]), "=r"(r[2]), "=r"(r[3]) : "r"(a));
}

__device__ __forceinline__ void mma_bf16(float* d, const unsigned* a, const unsigned* b) {
    asm volatile(
        "mma.sync.aligned.m16n8k16.row.col.f32.bf16.bf16.f32 "
        "{%0,%1,%2,%3}, {%4,%5,%6,%7}, {%8,%9}, {%0,%1,%2,%3};\n"
        : "+f"(d[0]), "+f"(d[1]), "+f"(d[2]), "+f"(d[3])
        : "r"(a[0]), "r"(a[1]), "r"(a[2]), "r"(a[3]), "r"(b[0]), "r"(b[1]));
}

// ---------------------------------------------------------------------------
// 1) prep: blocks [0,392) transpose 64px x 64ch + invnorm; [392,401) w split
// ---------------------------------------------------------------------------
__global__ void __launch_bounds__(256)
prep2_kernel(const float* __restrict__ x, const float* __restrict__ wgt) {
    const int id = blockIdx.x;
    const int t = threadIdx.x;

    if (id >= 392) {            // --- weight bf16 hi/lo split, [k][o*64+c] ---
        int k = id - 392;
#pragma unroll
        for (int s = 0; s < 16; s++) {
            int r = t * 16 + s;            // 0..4095
            int o = r >> 6, c = r & 63;
            float w = wgt[o * 576 + c * 9 + k];
            unsigned hp = bfpack(w, 0.0f);
            float res = w - __uint_as_float(hp << 16);
            unsigned lp = bfpack(res, 0.0f);
            g_wBh[k * 4096 + r] = (unsigned short)(hp & 0xFFFFu);
            g_wBl[k * 4096 + r] = (unsigned short)(lp & 0xFFFFu);
        }
        return;
    }

    __shared__ float s[64][67];
    int b = id / 49, pt = id - b * 49;
    int p0 = pt * 64;
    const float* xb = x + (size_t)b * CC * PP;
    float* xTb = g_xT + (size_t)b * PP * CC;

    const int v = t & 15, c0 = t >> 4;
    float4 ld[4];
#pragma unroll
    for (int i = 0; i < 4; i++)
        ld[i] = *(const float4*)(xb + (size_t)(c0 + 16 * i) * PP + p0 + 4 * v);
#pragma unroll
    for (int i = 0; i < 4; i++) {
        int c = c0 + 16 * i;
        s[c][4 * v + 0] = ld[i].x; s[c][4 * v + 1] = ld[i].y;
        s[c][4 * v + 2] = ld[i].z; s[c][4 * v + 3] = ld[i].w;
    }
    __syncthreads();

    const int p_l = t >> 4, v2 = t & 15;
#pragma unroll
    for (int i = 0; i < 4; i++) {
        int p = p_l + 16 * i;
        float4 o;
        o.x = s[4 * v2 + 0][p]; o.y = s[4 * v2 + 1][p];
        o.z = s[4 * v2 + 2][p]; o.w = s[4 * v2 + 3][p];
        *(float4*)(xTb + (size_t)(p0 + p) * CC + 4 * v2) = o;

        float sum = o.x * o.x + o.y * o.y + o.z * o.z + o.w * o.w;
        sum += __shfl_xor_sync(0xffffffffu, sum, 1);
        sum += __shfl_xor_sync(0xffffffffu, sum, 2);
        sum += __shfl_xor_sync(0xffffffffu, sum, 4);
        sum += __shfl_xor_sync(0xffffffffu, sum, 8);
        if (v2 == 0) g_invn[b * PP + p0 + p] = 1.0f / sqrtf(sum);
    }
}

// ---------------------------------------------------------------------------
// 3) simsel (unchanged; stores GLOBAL pixel indices b*PP + pick)
// ---------------------------------------------------------------------------
#define SROW 68

__global__ void __launch_bounds__(256)
simsel2_kernel() {
    __shared__ __align__(16) float sn[60 * SROW];

    const int t = threadIdx.x;
    const int j0 = blockIdx.x * 8;
    const int i  = blockIdx.y;
    const int b  = blockIdx.z;
    const float* xb   = g_xT + (size_t)b * PP * CC;
    const float* invb = g_invn + b * PP;

    {
        int slot = t >> 2, q = t & 3;
        if (slot < 60) {
            int ri = slot / 12, rj = slot - ri * 12;
            int gi = i - 2 + ri, gj = j0 - 2 + rj;
            if (gi >= 0 && gi < HH && gj >= 0 && gj < WW) {
                int gp = gi * WW + gj;
                const float* src = xb + (size_t)gp * CC;
                float iv = invb[gp];
                float* dst = sn + slot * SROW;
#pragma unroll
                for (int s = 0; s < 4; s++) {
                    int chunk = q + 4 * s;
                    float4 v = *(const float4*)(src + chunk * 4);
                    v.x *= iv; v.y *= iv; v.z *= iv; v.w *= iv;
                    *(float4*)(dst + 4 * ((chunk + ri) & 15)) = v;
                }
            }
        }
    }
    __syncthreads();

    const int lane = t & 31, w = t >> 5;
    const int j = j0 + w;

    int lo_i = (i - 2 < 0) ? 0 : i - 2;
    int hi_i = (i + 2 > HH - 1) ? HH - 1 : i + 2;
    int lo_j = (j - 2 < 0) ? 0 : j - 2;
    int hi_j = (j + 2 > WW - 1) ? WW - 1 : j + 2;
    int nrow = hi_i - lo_i + 1, ncol = hi_j - lo_j + 1;
    int ncand = nrow * ncol;

    unsigned mult = (65536u + (unsigned)ncol - 1) / (unsigned)ncol;
    int cr = (int)(((unsigned)lane * mult) >> 16);
    int cc = lane - cr * ncol;
    int ri = (lo_i - (i - 2)) + cr;
    int rj = (lo_j - (j0 - 2)) + cc;
    int slot = ri * 12 + rj;
    int rot_c = ri;
    if (lane >= ncand) { slot = 0; rot_c = 0; }
    int cpix = b * PP + (lo_i + cr) * WW + (lo_j + cc);   // GLOBAL index

    const float* crow = sn + slot * SROW;
    const float* prow = sn + (2 * 12 + (w + 2)) * SROW;

    int idx_c = rot_c & 15;
    int idx_p = 2;

    float2 aA = make_float2(0.f, 0.f), aB = make_float2(0.f, 0.f);
#pragma unroll
    for (int s = 0; s < 16; s++) {
        float4 cv = *(const float4*)(crow + 4 * idx_c);
        float4 pv = *(const float4*)(prow + 4 * idx_p);
        aA = ffma2(make_float2(cv.x, cv.y), make_float2(pv.x, pv.y), aA);
        aB = ffma2(make_float2(cv.z, cv.w), make_float2(pv.z, pv.w), aB);
        idx_c = (idx_c + 1) & 15;
        idx_p = (idx_p + 1) & 15;
    }
    float sim = (aA.x + aB.x) + (aA.y + aB.y);

    unsigned ub = __float_as_uint(sim);
    unsigned key = (ub & 0x80000000u) ? ~ub : (ub | 0x80000000u);
    if (lane >= ncand) key = 0xFFFFFFFFu;

    int mypick = 0;
#pragma unroll
    for (int r = 0; r < KK; r++) {
        unsigned m = __reduce_min_sync(0xffffffffu, key);
        unsigned ball = __ballot_sync(0xffffffffu, key == m);
        int bl = __ffs(ball) - 1;
        int wc = __shfl_sync(0xffffffffu, cpix, bl);
        if (lane == bl) key = 0xFFFFFFFFu;
        if (lane == r) mypick = wc;
    }

    int rank = 0;
#pragma unroll
    for (int r = 0; r < KK; r++) {
        int other = __shfl_sync(0xffffffffu, mypick, r);
        if (lane < KK && r != lane && other < mypick) rank++;
    }
    if (lane < KK)
        g_sel[((size_t)(b * PP + i * WW + j)) * KK + rank] = mypick;
}

// ---------------------------------------------------------------------------
// 4) conv_mma: HMMA split-product GEMM (R13 layout) with SOFTWARE-PIPELINED
//    A gather: LDG for chunk kc+1 issued before compute of kc (latency hidden
//    under 96 mma + 32 ldsm); cvt+STS of kc overlaps the W cp.async flight.
// ---------------------------------------------------------------------------
#define CM_SEL  0
#define CM_GH   4608                  // 128 rows * 144B
#define CM_GL   (CM_GH + 18432)
#define CM_WH   (CM_GL + 18432)       // 64 rows * 144B
#define CM_WL   (CM_WH + 9216)
#define CM_SMEM (CM_WL + 9216)        // 59904 B

__global__ void __launch_bounds__(256)
conv_mma_kernel(float* __restrict__ out) {
    extern __shared__ __align__(128) char sm[];
    unsigned sbase = (unsigned)__cvta_generic_to_shared(sm);
    int* selS = (int*)(sm + CM_SEL);

    const int tid = threadIdx.x;
    const int wid = tid >> 5, lane = tid & 31;
    const int tile = blockIdx.x;           // 196 tiles of 128 pixels

    for (int t2 = tid; t2 < 128 * KK; t2 += 256)
        selS[t2] = g_sel[(size_t)tile * 128 * KK + t2];

    const int qrow = tid >> 1;             // 0..127 pixel row (staging)
    const int ch0 = (tid & 1) * 32;        // channel half (staging)

    const int m0 = (wid & 3) * 32;         // warp pixel offset
    const int n0 = (wid >> 2) * 32;        // warp o offset

    // ldmatrix per-lane addresses
    const int arow = (lane & 7) + 8 * ((lane >> 3) & 1);
    const unsigned acol = (unsigned)(lane >> 4) * 16;
    const int brow = (lane & 7) + 8 * (lane >> 4);
    const unsigned bcol = (unsigned)((lane >> 3) & 1) * 16;

    const unsigned aAH0 = sbase + CM_GH + (unsigned)(m0 + arow) * 144 + acol;
    const unsigned aAH1 = aAH0 + 16 * 144;
    const unsigned aAL0 = aAH0 + (CM_GL - CM_GH);
    const unsigned aAL1 = aAH1 + (CM_GL - CM_GH);
    const unsigned aBH0 = sbase + CM_WH + (unsigned)(n0 + brow) * 144 + bcol;
    const unsigned aBH1 = aBH0 + 16 * 144;
    const unsigned aBL0 = aBH0 + (CM_WL - CM_WH);
    const unsigned aBL1 = aBH1 + (CM_WL - CM_WH);

    float acc[2][4][4];
#pragma unroll
    for (int mf = 0; mf < 2; mf++)
#pragma unroll
        for (int nf = 0; nf < 4; nf++)
#pragma unroll
            for (int r = 0; r < 4; r++) acc[mf][nf][r] = 0.0f;

    __syncthreads();   // selS visible

    // register prefetch of A rows for chunk 0
    float4 pv[8];
    {
        int rowg = selS[qrow * KK];
        const float4* src = (const float4*)(g_xT + (size_t)rowg * CC + ch0);
#pragma unroll
        for (int g = 0; g < 8; g++) pv[g] = src[g];
    }

    for (int kc = 0; kc < KK; kc++) {
        // --- stage W hi/lo via cp.async (issued first; flight overlaps cvt) ---
#pragma unroll
        for (int i = 0; i < 2; i++) {
            int e = tid + i * 256;             // 0..511
            int row = e >> 3, c16 = e & 7;
            unsigned doff = (unsigned)row * 144 + (unsigned)c16 * 16;
            cp16(sm + CM_WH + doff, (const char*)g_wBh + (size_t)kc * 8192 + (size_t)e * 16);
            cp16(sm + CM_WL + doff, (const char*)g_wBl + (size_t)kc * 8192 + (size_t)e * 16);
        }
        asm volatile("cp.async.commit_group;\n");

        // --- cvt + STS A(kc) from prefetched registers ---
#pragma unroll
        for (int g = 0; g < 8; g++) {
            float4 v = pv[g];
            unsigned h01 = bfpack(v.x, v.y);
            unsigned h23 = bfpack(v.z, v.w);
            float r0 = v.x - __uint_as_float(h01 << 16);
            float r1 = v.y - __uint_as_float(h01 & 0xFFFF0000u);
            float r2 = v.z - __uint_as_float(h23 << 16);
            float r3 = v.w - __uint_as_float(h23 & 0xFFFF0000u);
            unsigned l01 = bfpack(r0, r1);
            unsigned l23 = bfpack(r2, r3);
            unsigned off = (unsigned)qrow * 144 + (unsigned)(ch0 + 4 * g) * 2;
            *(uint2*)(sm + CM_GH + off) = make_uint2(h01, h23);
            *(uint2*)(sm + CM_GL + off) = make_uint2(l01, l23);
        }
        asm volatile("cp.async.wait_group 0;\n");
        __syncthreads();

        // --- prefetch A(kc+1) into registers; retires during compute ---
        if (kc + 1 < KK) {
            int rowg = selS[qrow * KK + kc + 1];
            const float4* src = (const float4*)(g_xT + (size_t)rowg * CC + ch0);
#pragma unroll
            for (int g = 0; g < 8; g++) pv[g] = src[g];
        }

        // --- compute: 4 k-steps of 16 ---
#pragma unroll
        for (int s = 0; s < 4; s++) {
            unsigned ks = (unsigned)s * 32;
            unsigned ah0[4], ah1[4], b0[4], b1[4], t0[4], t1[4];
            ldsm4(ah0, aAH0 + ks);
            ldsm4(ah1, aAH1 + ks);
            ldsm4(b0, aBH0 + ks);          // {nf0.b0, nf0.b1, nf1.b0, nf1.b1}
            ldsm4(b1, aBH1 + ks);          // nf2, nf3
            // Ah * Bh
            mma_bf16(acc[0][0], ah0, b0);     mma_bf16(acc[0][1], ah0, b0 + 2);
            mma_bf16(acc[0][2], ah0, b1);     mma_bf16(acc[0][3], ah0, b1 + 2);
            mma_bf16(acc[1][0], ah1, b0);     mma_bf16(acc[1][1], ah1, b0 + 2);
            mma_bf16(acc[1][2], ah1, b1);     mma_bf16(acc[1][3], ah1, b1 + 2);
            // Al * Bh
            ldsm4(t0, aAL0 + ks);
            ldsm4(t1, aAL1 + ks);
            mma_bf16(acc[0][0], t0, b0);      mma_bf16(acc[0][1], t0, b0 + 2);
            mma_bf16(acc[0][2], t0, b1);      mma_bf16(acc[0][3], t0, b1 + 2);
            mma_bf16(acc[1][0], t1, b0);      mma_bf16(acc[1][1], t1, b0 + 2);
            mma_bf16(acc[1][2], t1, b1);      mma_bf16(acc[1][3], t1, b1 + 2);
            // Ah * Bl
            ldsm4(b0, aBL0 + ks);
            ldsm4(b1, aBL1 + ks);
            mma_bf16(acc[0][0], ah0, b0);     mma_bf16(acc[0][1], ah0, b0 + 2);
            mma_bf16(acc[0][2], ah0, b1);     mma_bf16(acc[0][3], ah0, b1 + 2);
            mma_bf16(acc[1][0], ah1, b0);     mma_bf16(acc[1][1], ah1, b0 + 2);
            mma_bf16(acc[1][2], ah1, b1);     mma_bf16(acc[1][3], ah1, b1 + 2);
        }
        __syncthreads();    // all reads done before next chunk overwrites
    }

    // --- epilogue: C[px][o] -> out[b][o][p] ---
#pragma unroll
    for (int mf = 0; mf < 2; mf++) {
        int q0p = tile * 128 + m0 + 16 * mf + (lane >> 2);
        int q1p = q0p + 8;
        int b0i = q0p / PP, b1i = q1p / PP;
        float* ptr0 = out + (size_t)b0i * CC * PP + (q0p - b0i * PP);
        float* ptr1 = out + (size_t)b1i * CC * PP + (q1p - b1i * PP);
#pragma unroll
        for (int nf = 0; nf < 4; nf++) {
            int o = n0 + 8 * nf + (lane & 3) * 2;
            ptr0[(size_t)o * PP]       = acc[mf][nf][0];
            ptr0[(size_t)(o + 1) * PP] = acc[mf][nf][1];
            ptr1[(size_t)o * PP]       = acc[mf][nf][2];
            ptr1[(size_t)(o + 1) * PP] = acc[mf][nf][3];
        }
    }
}

// ---------------------------------------------------------------------------
extern "C" void kernel_launch(void* const* d_in, const int* in_sizes, int n_in,
                              void* d_out, int out_size) {
    const float* x = (const float*)d_in[0];   // [8,64,56,56]
    const float* w = (const float*)d_in[1];   // [64,64,3,3]
    float* out = (float*)d_out;               // [8,64,56,56]

    cudaFuncSetAttribute(conv_mma_kernel,
                         cudaFuncAttributeMaxDynamicSharedMemorySize, CM_SMEM);

    prep2_kernel<<<401, 256>>>(x, w);
    simsel2_kernel<<<dim3(7, 56, 8), 256>>>();
    conv_mma_kernel<<<196, 256, CM_SMEM>>>(out);
}

// round 17
// speedup vs baseline: 1.5719x; 1.0424x over previous
#include <cuda_runtime.h>
#include <cuda_bf16.h>

#define HH 56
#define WW 56
#define PP 3136   // HH*WW
#define BB 8
#define CC 64
#define KK 9      // 3x3

// Scratch (device globals)
__device__ float g_xT[BB * PP * CC];            // x transposed: [b][p][c]
__device__ float g_invn[BB * PP];               // 1/||x[b,:,p]||
__device__ int   g_sel[BB * PP * KK];           // sorted GLOBAL gather indices
__device__ unsigned short g_wBh[KK * 4096];     // W bf16 hi:  [k][o*64+c]
__device__ unsigned short g_wBl[KK * 4096];     // W bf16 lo residual

// ---------------------------------------------------------------------------
// helpers
// ---------------------------------------------------------------------------
__device__ __forceinline__ float2 ffma2(float2 a, float2 b, float2 c) {
    unsigned long long A, Bv, Cv;
    A  = *reinterpret_cast<unsigned long long*>(&a);
    Bv = *reinterpret_cast<unsigned long long*>(&b);
    Cv = *reinterpret_cast<unsigned long long*>(&c);
    unsigned long long R;
    asm("fma.rn.f32x2 %0, %1, %2, %3;" : "=l"(R) : "l"(A), "l"(Bv), "l"(Cv));
    return *reinterpret_cast<float2*>(&R);
}

__device__ __forceinline__ void cp16(void* sdst, const void* gsrc) {
    unsigned sa = (unsigned)__cvta_generic_to_shared(sdst);
    asm volatile("cp.async.cg.shared.global [%0], [%1], 16;\n" :: "r"(sa), "l"(gsrc));
}

// pack {lo, hi} floats -> bf16x2 (lo in low 16 bits)
__device__ __forceinline__ unsigned bfpack(float lo, float hi) {
    unsigned r;
    asm("cvt.rn.bf16x2.f32 %0, %1, %2;" : "=r"(r) : "f"(hi), "f"(lo));
    return r;
}

__device__ __forceinline__ void ldsm4(unsigned* r, unsigned a) {
    asm volatile("ldmatrix.sync.aligned.m8n8.x4.shared.b16 {%0,%1,%2,%3}, [%4];\n"
        : "=r"(r[0]), "=r"(r[1]), "=r"(r[2]), "=r"(r[3]) : "r"(a));
}

__device__ __forceinline__ void mma_bf16(float* d, const unsigned* a, const unsigned* b) {
    asm volatile(
        "mma.sync.aligned.m16n8k16.row.col.f32.bf16.bf16.f32 "
        "{%0,%1,%2,%3}, {%4,%5,%6,%7}, {%8,%9}, {%0,%1,%2,%3};\n"
        : "+f"(d[0]), "+f"(d[1]), "+f"(d[2]), "+f"(d[3])
        : "r"(a[0]), "r"(a[1]), "r"(a[2]), "r"(a[3]), "r"(b[0]), "r"(b[1]));
}

// ---------------------------------------------------------------------------
// 1) prep3: blocks [0,392) transpose 64px x 64ch + invnorm (512 threads for
//    2x resident-thread MLP); blocks [392,401) weight split.
// ---------------------------------------------------------------------------
__global__ void __launch_bounds__(512)
prep3_kernel(const float* __restrict__ x, const float* __restrict__ wgt) {
    const int id = blockIdx.x;
    const int t = threadIdx.x;

    if (id >= 392) {            // --- weight bf16 hi/lo split, [k][o*64+c] ---
        int k = id - 392;
#pragma unroll
        for (int s = 0; s < 8; s++) {
            int r = t * 8 + s;             // 0..4095
            int o = r >> 6, c = r & 63;
            float w = wgt[o * 576 + c * 9 + k];
            unsigned hp = bfpack(w, 0.0f);
            float res = w - __uint_as_float(hp << 16);
            unsigned lp = bfpack(res, 0.0f);
            g_wBh[k * 4096 + r] = (unsigned short)(hp & 0xFFFFu);
            g_wBl[k * 4096 + r] = (unsigned short)(lp & 0xFFFFu);
        }
        return;
    }

    __shared__ float s[64][67];
    int b = id / 49, pt = id - b * 49;
    int p0 = pt * 64;
    const float* xb = x + (size_t)b * CC * PP;
    float* xTb = g_xT + (size_t)b * PP * CC;

    // load: 1024 float4s, 2 per thread
#pragma unroll
    for (int h = 0; h < 2; h++) {
        int g = t + h * 512;
        int c = g >> 4, v = g & 15;
        float4 ld = *(const float4*)(xb + (size_t)c * PP + p0 + 4 * v);
        s[c][4 * v + 0] = ld.x; s[c][4 * v + 1] = ld.y;
        s[c][4 * v + 2] = ld.z; s[c][4 * v + 3] = ld.w;
    }
    __syncthreads();

    // store transposed + fused invnorm (16-lane groups per pixel)
#pragma unroll
    for (int h = 0; h < 2; h++) {
        int g = t + h * 512;
        int p = g >> 4, cv = g & 15;
        float4 o;
        o.x = s[4 * cv + 0][p]; o.y = s[4 * cv + 1][p];
        o.z = s[4 * cv + 2][p]; o.w = s[4 * cv + 3][p];
        *(float4*)(xTb + (size_t)(p0 + p) * CC + 4 * cv) = o;

        float sum = o.x * o.x + o.y * o.y + o.z * o.z + o.w * o.w;
        sum += __shfl_xor_sync(0xffffffffu, sum, 1);
        sum += __shfl_xor_sync(0xffffffffu, sum, 2);
        sum += __shfl_xor_sync(0xffffffffu, sum, 4);
        sum += __shfl_xor_sync(0xffffffffu, sum, 8);
        if (cv == 0) g_invn[b * PP + p0 + p] = 1.0f / sqrtf(sum);
    }
}

// ---------------------------------------------------------------------------
// 3) simsel3: block = 8x4 pixels (32 warps). Halo = 8 rows x 12 cols = 96
//    normalized vectors (3 per pixel vs 7.5 before). Same rotation scheme
//    (rot = halo row ri, 0..7): crow LDS conflict-free, prow broadcast.
//    Stores GLOBAL pixel indices b*PP + pick, sorted ascending.
// ---------------------------------------------------------------------------
#define SROW 68

__global__ void __launch_bounds__(1024)
simsel3_kernel() {
    __shared__ __align__(16) float sn[96 * SROW];

    const int t = threadIdx.x;
    const int j0 = blockIdx.x * 8;      // 56/8 = 7
    const int i0 = blockIdx.y * 4;      // 56/4 = 14
    const int b  = blockIdx.z;
    const float* xb   = g_xT + (size_t)b * PP * CC;
    const float* invb = g_invn + b * PP;

    // stage halo: rows i0-2..i0+5, cols j0-2..j0+9; 8 threads per slot
    if (t < 768) {
        int slot = t >> 3, q = t & 7;      // chunks q, q+8
        int ri = slot / 12, rj = slot - ri * 12;
        int gi = i0 - 2 + ri, gj = j0 - 2 + rj;
        if (gi >= 0 && gi < HH && gj >= 0 && gj < WW) {
            int gp = gi * WW + gj;
            const float* src = xb + (size_t)gp * CC;
            float iv = invb[gp];
            float* dst = sn + slot * SROW;
#pragma unroll
            for (int s = 0; s < 2; s++) {
                int chunk = q + 8 * s;
                float4 v = *(const float4*)(src + chunk * 4);
                v.x *= iv; v.y *= iv; v.z *= iv; v.w *= iv;
                *(float4*)(dst + 4 * ((chunk + ri) & 15)) = v;
            }
        }
    }
    __syncthreads();

    const int lane = t & 31, w = t >> 5;
    const int wr = w >> 3, wc = w & 7;     // pixel row/col within block
    const int i = i0 + wr, j = j0 + wc;

    int lo_i = (i - 2 < 0) ? 0 : i - 2;
    int hi_i = (i + 2 > HH - 1) ? HH - 1 : i + 2;
    int lo_j = (j - 2 < 0) ? 0 : j - 2;
    int hi_j = (j + 2 > WW - 1) ? WW - 1 : j + 2;
    int nrow = hi_i - lo_i + 1, ncol = hi_j - lo_j + 1;
    int ncand = nrow * ncol;

    unsigned mult = (65536u + (unsigned)ncol - 1) / (unsigned)ncol;
    int cr = (int)(((unsigned)lane * mult) >> 16);
    int cc = lane - cr * ncol;
    int ri = (lo_i - (i0 - 2)) + cr;       // halo row 0..7
    int rj = (lo_j - (j0 - 2)) + cc;
    int slot = ri * 12 + rj;
    int rot_c = ri;
    if (lane >= ncand) { slot = 0; rot_c = 0; }
    int cpix = b * PP + (lo_i + cr) * WW + (lo_j + cc);   // GLOBAL index

    const float* crow = sn + slot * SROW;
    const float* prow = sn + ((wr + 2) * 12 + (wc + 2)) * SROW;
    const int rot_p = wr + 2;

    int idx_c = rot_c & 15;
    int idx_p = rot_p & 15;

    float2 aA = make_float2(0.f, 0.f), aB = make_float2(0.f, 0.f);
#pragma unroll
    for (int s = 0; s < 16; s++) {
        float4 cv = *(const float4*)(crow + 4 * idx_c);
        float4 pv = *(const float4*)(prow + 4 * idx_p);
        aA = ffma2(make_float2(cv.x, cv.y), make_float2(pv.x, pv.y), aA);
        aB = ffma2(make_float2(cv.z, cv.w), make_float2(pv.z, pv.w), aB);
        idx_c = (idx_c + 1) & 15;
        idx_p = (idx_p + 1) & 15;
    }
    float sim = (aA.x + aB.x) + (aA.y + aB.y);

    unsigned ub = __float_as_uint(sim);
    unsigned key = (ub & 0x80000000u) ? ~ub : (ub | 0x80000000u);
    if (lane >= ncand) key = 0xFFFFFFFFu;

    int mypick = 0;
#pragma unroll
    for (int r = 0; r < KK; r++) {
        unsigned m = __reduce_min_sync(0xffffffffu, key);
        unsigned ball = __ballot_sync(0xffffffffu, key == m);
        int bl = __ffs(ball) - 1;
        int wc2 = __shfl_sync(0xffffffffu, cpix, bl);
        if (lane == bl) key = 0xFFFFFFFFu;
        if (lane == r) mypick = wc2;
    }

    int rank = 0;
#pragma unroll
    for (int r = 0; r < KK; r++) {
        int other = __shfl_sync(0xffffffffu, mypick, r);
        if (lane < KK && r != lane && other < mypick) rank++;
    }
    if (lane < KK)
        g_sel[((size_t)(b * PP + i * WW + j)) * KK + rank] = mypick;
}

// ---------------------------------------------------------------------------
// 4) conv_mma: HMMA split-product GEMM (unchanged from R15)
// ---------------------------------------------------------------------------
#define CM_SEL  0
#define CM_GH   4608                  // 128 rows * 144B
#define CM_GL   (CM_GH + 18432)
#define CM_WH   (CM_GL + 18432)       // 64 rows * 144B
#define CM_WL   (CM_WH + 9216)
#define CM_SMEM (CM_WL + 9216)        // 59904 B

__global__ void __launch_bounds__(256)
conv_mma_kernel(float* __restrict__ out) {
    extern __shared__ __align__(128) char sm[];
    unsigned sbase = (unsigned)__cvta_generic_to_shared(sm);
    int* selS = (int*)(sm + CM_SEL);

    const int tid = threadIdx.x;
    const int wid = tid >> 5, lane = tid & 31;
    const int tile = blockIdx.x;           // 196 tiles of 128 pixels

    for (int t2 = tid; t2 < 128 * KK; t2 += 256)
        selS[t2] = g_sel[(size_t)tile * 128 * KK + t2];

    const int qrow = tid >> 1;             // 0..127 pixel row (staging)
    const int ch0 = (tid & 1) * 32;        // channel half (staging)

    const int m0 = (wid & 3) * 32;         // warp pixel offset
    const int n0 = (wid >> 2) * 32;        // warp o offset

    // ldmatrix per-lane addresses
    const int arow = (lane & 7) + 8 * ((lane >> 3) & 1);
    const unsigned acol = (unsigned)(lane >> 4) * 16;
    const int brow = (lane & 7) + 8 * (lane >> 4);
    const unsigned bcol = (unsigned)((lane >> 3) & 1) * 16;

    const unsigned aAH0 = sbase + CM_GH + (unsigned)(m0 + arow) * 144 + acol;
    const unsigned aAH1 = aAH0 + 16 * 144;
    const unsigned aAL0 = aAH0 + (CM_GL - CM_GH);
    const unsigned aAL1 = aAH1 + (CM_GL - CM_GH);
    const unsigned aBH0 = sbase + CM_WH + (unsigned)(n0 + brow) * 144 + bcol;
    const unsigned aBH1 = aBH0 + 16 * 144;
    const unsigned aBL0 = aBH0 + (CM_WL - CM_WH);
    const unsigned aBL1 = aBH1 + (CM_WL - CM_WH);

    float acc[2][4][4];
#pragma unroll
    for (int mf = 0; mf < 2; mf++)
#pragma unroll
        for (int nf = 0; nf < 4; nf++)
#pragma unroll
            for (int r = 0; r < 4; r++) acc[mf][nf][r] = 0.0f;

    __syncthreads();   // selS visible

    // register prefetch of A rows for chunk 0
    float4 pv[8];
    {
        int rowg = selS[qrow * KK];
        const float4* src = (const float4*)(g_xT + (size_t)rowg * CC + ch0);
#pragma unroll
        for (int g = 0; g < 8; g++) pv[g] = src[g];
    }

    for (int kc = 0; kc < KK; kc++) {
        // --- stage W hi/lo via cp.async (flight overlaps cvt) ---
#pragma unroll
        for (int i = 0; i < 2; i++) {
            int e = tid + i * 256;             // 0..511
            int row = e >> 3, c16 = e & 7;
            unsigned doff = (unsigned)row * 144 + (unsigned)c16 * 16;
            cp16(sm + CM_WH + doff, (const char*)g_wBh + (size_t)kc * 8192 + (size_t)e * 16);
            cp16(sm + CM_WL + doff, (const char*)g_wBl + (size_t)kc * 8192 + (size_t)e * 16);
        }
        asm volatile("cp.async.commit_group;\n");

        // --- cvt + STS A(kc) from prefetched registers ---
#pragma unroll
        for (int g = 0; g < 8; g++) {
            float4 v = pv[g];
            unsigned h01 = bfpack(v.x, v.y);
            unsigned h23 = bfpack(v.z, v.w);
            float r0 = v.x - __uint_as_float(h01 << 16);
            float r1 = v.y - __uint_as_float(h01 & 0xFFFF0000u);
            float r2 = v.z - __uint_as_float(h23 << 16);
            float r3 = v.w - __uint_as_float(h23 & 0xFFFF0000u);
            unsigned l01 = bfpack(r0, r1);
            unsigned l23 = bfpack(r2, r3);
            unsigned off = (unsigned)qrow * 144 + (unsigned)(ch0 + 4 * g) * 2;
            *(uint2*)(sm + CM_GH + off) = make_uint2(h01, h23);
            *(uint2*)(sm + CM_GL + off) = make_uint2(l01, l23);
        }
        asm volatile("cp.async.wait_group 0;\n");
        __syncthreads();

        // --- prefetch A(kc+1) into registers; retires during compute ---
        if (kc + 1 < KK) {
            int rowg = selS[qrow * KK + kc + 1];
            const float4* src = (const float4*)(g_xT + (size_t)rowg * CC + ch0);
#pragma unroll
            for (int g = 0; g < 8; g++) pv[g] = src[g];
        }

        // --- compute: 4 k-steps of 16 ---
#pragma unroll
        for (int s = 0; s < 4; s++) {
            unsigned ks = (unsigned)s * 32;
            unsigned ah0[4], ah1[4], b0[4], b1[4], t0[4], t1[4];
            ldsm4(ah0, aAH0 + ks);
            ldsm4(ah1, aAH1 + ks);
            ldsm4(b0, aBH0 + ks);          // {nf0.b0, nf0.b1, nf1.b0, nf1.b1}
            ldsm4(b1, aBH1 + ks);          // nf2, nf3
            // Ah * Bh
            mma_bf16(acc[0][0], ah0, b0);     mma_bf16(acc[0][1], ah0, b0 + 2);
            mma_bf16(acc[0][2], ah0, b1);     mma_bf16(acc[0][3], ah0, b1 + 2);
            mma_bf16(acc[1][0], ah1, b0);     mma_bf16(acc[1][1], ah1, b0 + 2);
            mma_bf16(acc[1][2], ah1, b1);     mma_bf16(acc[1][3], ah1, b1 + 2);
            // Al * Bh
            ldsm4(t0, aAL0 + ks);
            ldsm4(t1, aAL1 + ks);
            mma_bf16(acc[0][0], t0, b0);      mma_bf16(acc[0][1], t0, b0 + 2);
            mma_bf16(acc[0][2], t0, b1);      mma_bf16(acc[0][3], t0, b1 + 2);
            mma_bf16(acc[1][0], t1, b0);      mma_bf16(acc[1][1], t1, b0 + 2);
            mma_bf16(acc[1][2], t1, b1);      mma_bf16(acc[1][3], t1, b1 + 2);
            // Ah * Bl
            ldsm4(b0, aBL0 + ks);
            ldsm4(b1, aBL1 + ks);
            mma_bf16(acc[0][0], ah0, b0);     mma_bf16(acc[0][1], ah0, b0 + 2);
            mma_bf16(acc[0][2], ah0, b1);     mma_bf16(acc[0][3], ah0, b1 + 2);
            mma_bf16(acc[1][0], ah1, b0);     mma_bf16(acc[1][1], ah1, b0 + 2);
            mma_bf16(acc[1][2], ah1, b1);     mma_bf16(acc[1][3], ah1, b1 + 2);
        }
        __syncthreads();    // all reads done before next chunk overwrites
    }

    // --- epilogue: C[px][o] -> out[b][o][p] ---
#pragma unroll
    for (int mf = 0; mf < 2; mf++) {
        int q0p = tile * 128 + m0 + 16 * mf + (lane >> 2);
        int q1p = q0p + 8;
        int b0i = q0p / PP, b1i = q1p / PP;
        float* ptr0 = out + (size_t)b0i * CC * PP + (q0p - b0i * PP);
        float* ptr1 = out + (size_t)b1i * CC * PP + (q1p - b1i * PP);
#pragma unroll
        for (int nf = 0; nf < 4; nf++) {
            int o = n0 + 8 * nf + (lane & 3) * 2;
            ptr0[(size_t)o * PP]       = acc[mf][nf][0];
            ptr0[(size_t)(o + 1) * PP] = acc[mf][nf][1];
            ptr1[(size_t)o * PP]       = acc[mf][nf][2];
            ptr1[(size_t)(o + 1) * PP] = acc[mf][nf][3];
        }
    }
}

// ---------------------------------------------------------------------------
extern "C" void kernel_launch(void* const* d_in, const int* in_sizes, int n_in,
                              void* d_out, int out_size) {
    const float* x = (const float*)d_in[0];   // [8,64,56,56]
    const float* w = (const float*)d_in[1];   // [64,64,3,3]
    float* out = (float*)d_out;               // [8,64,56,56]

    cudaFuncSetAttribute(conv_mma_kernel,
                         cudaFuncAttributeMaxDynamicSharedMemorySize, CM_SMEM);

    prep3_kernel<<<401, 512>>>(x, w);
    simsel3_kernel<<<dim3(7, 14, 8), 1024>>>();
    conv_mma_kernel<<<196, 256, CM_SMEM>>>(out);
}